// round 10
// baseline (speedup 1.0000x reference)
#include <cuda_runtime.h>
#include <cuda_pipeline.h>

#define BB 8
#define SS 2048
#define DD 768
#define NSP 512
#define MAXW 30
#define HH 100
#define M_TOTAL (BB*NSP)   /* 4096 */

__device__ float g_logits[BB*SS];
__device__ float g_att[(size_t)M_TOTAL*DD];

typedef unsigned long long ull;

__device__ __forceinline__ void f32x2_fma(ull& acc, ull a, ull b) {
    asm("fma.rn.f32x2 %0, %1, %2, %0;" : "+l"(acc) : "l"(a), "l"(b));
}
__device__ __forceinline__ float2 f32x2_unpack(ull v) {
    unsigned int lo, hi;
    asm("mov.b64 {%0, %1}, %2;" : "=r"(lo), "=r"(hi) : "l"(v));
    return make_float2(__uint_as_float(lo), __uint_as_float(hi));
}

// -------- Kernel 1: logits via 4-deep cp.async ring -----------------------------
// grid = 1024, block = 128 (4 warps). 16 rows/block = 4 stages x 4 rows (12KB each).
// All 4 stages committed up-front: 48KB in flight per block, 4 blocks/SM.
__global__ void __launch_bounds__(128) k_logits(const float* __restrict__ seq,
                                                const float* __restrict__ att_w,
                                                const float* __restrict__ att_b) {
    __shared__ float4 sbuf[4][4 * (DD / 4)];   // 4 x 12KB = 48KB

    int tid = threadIdx.x, warp = tid >> 5, lane = tid & 31;
    size_t base = (size_t)blockIdx.x * 16;
    const float4* src = (const float4*)seq + base * (DD / 4);

#pragma unroll
    for (int st = 0; st < 4; st++) {
#pragma unroll
        for (int k = 0; k < 6; k++) {
            int idx = tid + k * 128;
            __pipeline_memcpy_async(&sbuf[st][idx], &src[st * 768 + idx], 16);
        }
        __pipeline_commit();
    }

    float4 wreg[6];
    const float4* w4 = (const float4*)att_w;
#pragma unroll
    for (int j = 0; j < 6; j++) wreg[j] = __ldg(&w4[lane + 32 * j]);
    float bconst = __ldg(att_b);

#pragma unroll
    for (int s = 0; s < 4; s++) {
        switch (s) {
            case 0: __pipeline_wait_prior(3); break;
            case 1: __pipeline_wait_prior(2); break;
            case 2: __pipeline_wait_prior(1); break;
            default: __pipeline_wait_prior(0); break;
        }
        __syncthreads();

        const float4* row = &sbuf[s][warp * (DD / 4)];
        float4 x[6];
#pragma unroll
        for (int j = 0; j < 6; j++) x[j] = row[lane + 32 * j];
        ull acc = 0ull;
#pragma unroll
        for (int j = 0; j < 6; j++) {
            const ull* xp = (const ull*)&x[j];
            const ull* wp = (const ull*)&wreg[j];
            f32x2_fma(acc, xp[0], wp[0]);
            f32x2_fma(acc, xp[1], wp[1]);
        }
        float2 p = f32x2_unpack(acc);
        float sum = p.x + p.y;
#pragma unroll
        for (int o = 16; o > 0; o >>= 1) sum += __shfl_xor_sync(0xffffffffu, sum, o);
        if (lane == 0) g_logits[base + s * 4 + warp] = sum + bconst;
    }
}

// ---------------- Kernel 2: per-span softmax + weighted sum (seq L2-hot) -------
__global__ void k_span(const float* __restrict__ seq,
                       const int* __restrict__ spans,
                       const int* __restrict__ mask) {
    __shared__ float s_attn[MAXW];
    __shared__ int   s_start, s_cnt;
    int sp  = blockIdx.x;
    int b   = sp >> 9;
    int tid = threadIdx.x;

    if (tid < 32) {
        int start = spans[sp * 2];
        int cnt   = spans[sp * 2 + 1] - start;        // width 1..30
        float lg = (tid < cnt) ? g_logits[b * SS + start + tid] : -1e30f;
        float mx = lg;
#pragma unroll
        for (int o = 16; o > 0; o >>= 1) mx = fmaxf(mx, __shfl_xor_sync(0xffffffffu, mx, o));
        float ex = (tid < cnt) ? expf(lg - mx) : 0.f;
        float sm = ex;
#pragma unroll
        for (int o = 16; o > 0; o >>= 1) sm += __shfl_xor_sync(0xffffffffu, sm, o);
        float mk = (float)mask[sp];
        if (tid < MAXW) s_attn[tid] = ex / sm * mk;
        if (tid == 0) { s_start = start; s_cnt = cnt; }
    }
    __syncthreads();

    int start = s_start, cnt = s_cnt;
    const float4* base = (const float4*)seq + (size_t)(b * SS + start) * (DD / 4) + tid;
    float4 acc = make_float4(0.f, 0.f, 0.f, 0.f);
#pragma unroll 4
    for (int w = 0; w < cnt; w++) {
        float a  = s_attn[w];
        float4 v = base[(size_t)w * (DD / 4)];
        acc.x += a * v.x; acc.y += a * v.y; acc.z += a * v.z; acc.w += a * v.w;
    }
    ((float4*)g_att)[(size_t)sp * (DD / 4) + tid] = acc;
}

// ---- Kernel 3: GEMM + bias + tanh, 3-way in-block split-K, dup-A, no packs ----
// grid = 128 (M-tile 32), block = 672 = 21 warps (3 thirds x 7 col-groups).
// Thread: rows {r, r+16} x cols [wg*16+cs*8, +8). Per kk: 2 LDS.64 (dup A)
// + 2 LDS.128 (W bcast) + 8 FMA2 -> 16 MACs, 12 instr. 5.25 warps/SMSP.
#define KC 48
#define NA_F4 ((32*KC)/4)    /* 384 */
#define NW_F4 ((KC*HH)/4)    /* 1200 */

__global__ void __launch_bounds__(672) k_gemm(const float* __restrict__ W,
                                              const float* __restrict__ bias,
                                              float* __restrict__ out) {
    __shared__ float sAd[KC][72];      // duplicated A: [kk][2r]==[kk][2r+1]
    __shared__ float sW[KC][112];      // cols [100,112) zero-padded once
    __shared__ float sC[2][224][18];   // partials of thirds 1,2
    __shared__ float sB[HH];

    int m0   = blockIdx.x * 32;
    int tid  = threadIdx.x;
    int warp = tid >> 5, lane = tid & 31;
    int third = warp / 7;
    int wg    = warp % 7;
    int r     = lane & 15;
    int cs    = lane >> 4;
    int col   = wg * 16 + cs * 8;      // up to 104; guarded at store
    int lidx  = wg * 32 + lane;        // 0..223 local id within third

    if (tid < HH) sB[tid] = bias[tid];
    for (int i = tid; i < 12 * KC; i += 672) { int kk = i / 12; sW[kk][100 + i % 12] = 0.f; }

    const float4* A4 = (const float4*)g_att;
    const float4* W4 = (const float4*)W;

    int aIdx  = tid;                       // <384: row = aIdx/12, kf4 = aIdx%12
    int wIdx0 = tid, wIdx1 = tid + 672;    // <1200: kk = idx/25, c4 = idx%25

    float4 ra, rw0, rw1;
    if (aIdx < NA_F4)  ra  = A4[(size_t)(m0 + aIdx / 12) * (DD/4) + aIdx % 12];
    if (wIdx0 < NW_F4) rw0 = W4[(size_t)(wIdx0 / 25) * (HH/4) + wIdx0 % 25];
    if (wIdx1 < NW_F4) rw1 = W4[(size_t)(wIdx1 / 25) * (HH/4) + wIdx1 % 25];

    ull acc[8];
#pragma unroll
    for (int i = 0; i < 8; i++) acc[i] = 0ull;

    for (int kc = 0; kc < DD; kc += KC) {
        if (aIdx < NA_F4) {
            int row = aIdx / 12, kf = (aIdx % 12) * 4;
            float2* d0 = (float2*)&sAd[kf+0][2*row]; *d0 = make_float2(ra.x, ra.x);
            float2* d1 = (float2*)&sAd[kf+1][2*row]; *d1 = make_float2(ra.y, ra.y);
            float2* d2 = (float2*)&sAd[kf+2][2*row]; *d2 = make_float2(ra.z, ra.z);
            float2* d3 = (float2*)&sAd[kf+3][2*row]; *d3 = make_float2(ra.w, ra.w);
        }
        if (wIdx0 < NW_F4) { int kk = wIdx0 / 25, c = (wIdx0 % 25) * 4; *(float4*)&sW[kk][c] = rw0; }
        if (wIdx1 < NW_F4) { int kk = wIdx1 / 25, c = (wIdx1 % 25) * 4; *(float4*)&sW[kk][c] = rw1; }
        __syncthreads();

        int kn = kc + KC;
        if (kn < DD) {
            if (aIdx < NA_F4)  ra  = A4[(size_t)(m0 + aIdx / 12) * (DD/4) + (kn >> 2) + aIdx % 12];
            if (wIdx0 < NW_F4) rw0 = W4[(size_t)(kn + wIdx0 / 25) * (HH/4) + wIdx0 % 25];
            if (wIdx1 < NW_F4) rw1 = W4[(size_t)(kn + wIdx1 / 25) * (HH/4) + wIdx1 % 25];
        }

        int kbase = third * 16;
#pragma unroll
        for (int k2 = 0; k2 < 16; k2++) {
            int kk = kbase + k2;
            ull a0 = *(const ull*)&sAd[kk][2 * r];
            ull a1 = *(const ull*)&sAd[kk][2 * r + 32];
            float4 w0 = *(const float4*)&sW[kk][col];
            float4 w1 = *(const float4*)&sW[kk][col + 4];
            const ull* wp0 = (const ull*)&w0;
            const ull* wp1 = (const ull*)&w1;
            f32x2_fma(acc[0], a0, wp0[0]);
            f32x2_fma(acc[1], a0, wp0[1]);
            f32x2_fma(acc[2], a0, wp1[0]);
            f32x2_fma(acc[3], a0, wp1[1]);
            f32x2_fma(acc[4], a1, wp0[0]);
            f32x2_fma(acc[5], a1, wp0[1]);
            f32x2_fma(acc[6], a1, wp1[0]);
            f32x2_fma(acc[7], a1, wp1[1]);
        }
        __syncthreads();
    }

    // thirds 1,2 dump partials; third 0 combines + bias + tanh + store
    if (third > 0) {
        float* dst = &sC[third - 1][lidx][0];
#pragma unroll
        for (int i = 0; i < 8; i++) {
            float2 p = f32x2_unpack(acc[i]);
            dst[i * 2] = p.x; dst[i * 2 + 1] = p.y;
        }
    }
    __syncthreads();

    if (third == 0) {
        const float* s1 = &sC[0][lidx][0];
        const float* s2 = &sC[1][lidx][0];
        float v[16];
#pragma unroll
        for (int i = 0; i < 8; i++) {
            float2 p = f32x2_unpack(acc[i]);
            v[i * 2]     = p.x + s1[i * 2]     + s2[i * 2];
            v[i * 2 + 1] = p.y + s1[i * 2 + 1] + s2[i * 2 + 1];
        }
#pragma unroll
        for (int rr = 0; rr < 2; rr++) {
            size_t row = (size_t)(m0 + r + rr * 16);
            if (col < HH) {
                float4 o;
                o.x = tanhf(v[rr*8+0] + sB[col+0]);
                o.y = tanhf(v[rr*8+1] + sB[col+1]);
                o.z = tanhf(v[rr*8+2] + sB[col+2]);
                o.w = tanhf(v[rr*8+3] + sB[col+3]);
                *(float4*)&out[row * HH + col] = o;
            }
            if (col + 4 < HH) {
                float4 o;
                o.x = tanhf(v[rr*8+4] + sB[col+4]);
                o.y = tanhf(v[rr*8+5] + sB[col+5]);
                o.z = tanhf(v[rr*8+6] + sB[col+6]);
                o.w = tanhf(v[rr*8+7] + sB[col+7]);
                *(float4*)&out[row * HH + col + 4] = o;
            }
        }
    }
}

extern "C" void kernel_launch(void* const* d_in, const int* in_sizes, int n_in,
                              void* d_out, int out_size) {
    const float* seq   = (const float*)d_in[0];
    const int*   spans = (const int*)d_in[1];
    const int*   mask  = (const int*)d_in[2];
    const float* att_w = (const float*)d_in[3];
    const float* att_b = (const float*)d_in[4];
    const float* ffn_w = (const float*)d_in[5];
    const float* ffn_b = (const float*)d_in[6];
    float*       out   = (float*)d_out;

    k_logits<<<1024, 128>>>(seq, att_w, att_b);
    k_span<<<M_TOTAL, 192>>>(seq, spans, mask);
    k_gemm<<<128, 672>>>(ffn_w, ffn_b, out);
}

// round 11
// speedup vs baseline: 1.1828x; 1.1828x over previous
#include <cuda_runtime.h>
#include <cuda_pipeline.h>

#define BB 8
#define SS 2048
#define DD 768
#define NSP 512
#define MAXW 30
#define HH 100
#define M_TOTAL (BB*NSP)   /* 4096 */

__device__ float g_logits[BB*SS];
__device__ float g_att[(size_t)M_TOTAL*DD];

typedef unsigned long long ull;

__device__ __forceinline__ void f32x2_fma(ull& acc, ull a, ull b) {
    asm("fma.rn.f32x2 %0, %1, %2, %0;" : "+l"(acc) : "l"(a), "l"(b));
}
__device__ __forceinline__ ull f32x2_pack(float x, float y) {
    ull r;
    asm("mov.b64 %0, {%1, %2};" : "=l"(r) : "r"(__float_as_uint(x)), "r"(__float_as_uint(y)));
    return r;
}
__device__ __forceinline__ float2 f32x2_unpack(ull v) {
    unsigned int lo, hi;
    asm("mov.b64 {%0, %1}, %2;" : "=r"(lo), "=r"(hi) : "l"(v));
    return make_float2(__uint_as_float(lo), __uint_as_float(hi));
}

// -------- Kernel 1: logits via 4-deep cp.async ring (R9, proven 11.8us) --------
__global__ void __launch_bounds__(256) k_logits(const float* __restrict__ seq,
                                                const float* __restrict__ att_w,
                                                const float* __restrict__ att_b) {
    __shared__ float4 sbuf[2][8 * (DD / 4)];     // 2 x 24KB

    int tid = threadIdx.x, warp = tid >> 5, lane = tid & 31;
    size_t base = (size_t)blockIdx.x * 32;
    const float4* src = (const float4*)seq + base * (DD / 4);

#pragma unroll
    for (int k = 0; k < 6; k++) {
        int idx = tid + k * 256;
        __pipeline_memcpy_async(&sbuf[0][idx], &src[idx], 16);
    }
    __pipeline_commit();
#pragma unroll
    for (int k = 0; k < 6; k++) {
        int idx = tid + k * 256;
        __pipeline_memcpy_async(&sbuf[1][idx], &src[1536 + idx], 16);
    }
    __pipeline_commit();

    float4 wreg[6];
    const float4* w4 = (const float4*)att_w;
#pragma unroll
    for (int j = 0; j < 6; j++) wreg[j] = __ldg(&w4[lane + 32 * j]);
    float bconst = __ldg(att_b);

    for (int s = 0; s < 4; s++) {
        if (s < 3) __pipeline_wait_prior(1);
        else       __pipeline_wait_prior(0);
        __syncthreads();

        const float4* row = &sbuf[s & 1][warp * (DD / 4)];
        float4 x[6];
#pragma unroll
        for (int j = 0; j < 6; j++) x[j] = row[lane + 32 * j];
        ull acc = 0ull;
#pragma unroll
        for (int j = 0; j < 6; j++) {
            const ull* xp = (const ull*)&x[j];
            const ull* wp = (const ull*)&wreg[j];
            f32x2_fma(acc, xp[0], wp[0]);
            f32x2_fma(acc, xp[1], wp[1]);
        }
        float2 p = f32x2_unpack(acc);
        float sum = p.x + p.y;
#pragma unroll
        for (int o = 16; o > 0; o >>= 1) sum += __shfl_xor_sync(0xffffffffu, sum, o);
        if (lane == 0) g_logits[base + s * 8 + warp] = sum + bconst;
        __syncthreads();

        if (s + 2 < 4) {
            const float4* g = src + (size_t)(s + 2) * 1536;
#pragma unroll
            for (int k = 0; k < 6; k++) {
                int idx = tid + k * 256;
                __pipeline_memcpy_async(&sbuf[s & 1][idx], &g[idx], 16);
            }
            __pipeline_commit();
        }
    }
}

// -------- Kernel 2: per-span softmax + weighted sum, full-width unroll ---------
__global__ void __launch_bounds__(192) k_span(const float* __restrict__ seq,
                                              const int* __restrict__ spans,
                                              const int* __restrict__ mask) {
    __shared__ float s_attn[MAXW];
    __shared__ int   s_start, s_cnt;
    int sp  = blockIdx.x;
    int b   = sp >> 9;
    int tid = threadIdx.x;

    if (tid < 32) {
        int start = spans[sp * 2];
        int cnt   = spans[sp * 2 + 1] - start;        // width 1..30
        float lg = (tid < cnt) ? g_logits[b * SS + start + tid] : -1e30f;
        float mx = lg;
#pragma unroll
        for (int o = 16; o > 0; o >>= 1) mx = fmaxf(mx, __shfl_xor_sync(0xffffffffu, mx, o));
        float ex = (tid < cnt) ? expf(lg - mx) : 0.f;
        float sm = ex;
#pragma unroll
        for (int o = 16; o > 0; o >>= 1) sm += __shfl_xor_sync(0xffffffffu, sm, o);
        float mk = (float)mask[sp];
        if (tid < MAXW) s_attn[tid] = ex / sm * mk;
        if (tid == 0) { s_start = start; s_cnt = cnt; }
    }
    __syncthreads();

    int start = s_start, cnt = s_cnt;
    const float4* base = (const float4*)seq + (size_t)(b * SS + start) * (DD / 4) + tid;
    float4 acc = make_float4(0.f, 0.f, 0.f, 0.f);
#pragma unroll
    for (int w = 0; w < MAXW; w++) {
        if (w < cnt) {
            float a  = s_attn[w];
            float4 v = base[(size_t)w * (DD / 4)];
            acc.x += a * v.x; acc.y += a * v.y; acc.z += a * v.z; acc.w += a * v.w;
        }
    }
    ((float4*)g_att)[(size_t)sp * (DD / 4) + tid] = acc;
}

// ---- Kernel 3: GEMM + bias + tanh, broadcast-W, split-K=2, smem ping-pong ----
// grid = 128 (M-tile 32), block = 448. ONE __syncthreads per chunk; STS of
// chunk c+1 overlaps compute of chunk c. Inner loop identical to proven R8.
#define KC 32
#define NA_F4 ((32*KC)/4)    /* 256 */
#define NW_F4 ((KC*HH)/4)    /* 800 */

__global__ void __launch_bounds__(448) k_gemm(const float* __restrict__ W,
                                              const float* __restrict__ bias,
                                              float* __restrict__ out) {
    __shared__ float sA[2][KC][36];
    __shared__ float sW[2][KC][112];   // cols [100,112) zero-padded once
    __shared__ float sC[224][20];
    __shared__ float sB[HH];

    int m0   = blockIdx.x * 32;
    int tid  = threadIdx.x;
    int warp = tid >> 5, lane = tid & 31;
    int half = warp / 7;
    int wg   = warp % 7;
    int r    = lane & 15;
    int cs   = lane >> 4;
    int col  = wg * 16 + cs * 8;

    if (tid < HH) sB[tid] = bias[tid];
    for (int i = tid; i < 2 * 12 * KC; i += 448) {
        int bf = i / (12 * KC), j = i % (12 * KC);
        sW[bf][j / 12][100 + j % 12] = 0.f;
    }

    const float4* A4 = (const float4*)g_att;
    const float4* W4 = (const float4*)W;

    int aIdx  = tid;
    int wIdx0 = tid, wIdx1 = tid + 448;

    float4 raA, rw0A, rw1A, raB, rw0B, rw1B;

    auto ldg = [&](int chunk, float4& ra, float4& rw0, float4& rw1) {
        int kn = chunk * KC;
        if (aIdx < NA_F4)  ra  = A4[(size_t)(m0 + (aIdx >> 3)) * (DD/4) + (kn >> 2) + (aIdx & 7)];
        if (wIdx0 < NW_F4) rw0 = W4[(size_t)(kn + wIdx0 / 25) * (HH/4) + wIdx0 % 25];
        if (wIdx1 < NW_F4) rw1 = W4[(size_t)(kn + wIdx1 / 25) * (HH/4) + wIdx1 % 25];
    };
    auto sts = [&](int bf, const float4& ra, const float4& rw0, const float4& rw1) {
        if (aIdx < NA_F4) { int row = aIdx >> 3, kf = (aIdx & 7) * 4;
            sA[bf][kf+0][row] = ra.x; sA[bf][kf+1][row] = ra.y;
            sA[bf][kf+2][row] = ra.z; sA[bf][kf+3][row] = ra.w; }
        if (wIdx0 < NW_F4) { int kk = wIdx0 / 25, c = (wIdx0 % 25) * 4; *(float4*)&sW[bf][kk][c] = rw0; }
        if (wIdx1 < NW_F4) { int kk = wIdx1 / 25, c = (wIdx1 % 25) * 4; *(float4*)&sW[bf][kk][c] = rw1; }
    };

    ull acc[8];
#pragma unroll
    for (int i = 0; i < 8; i++) acc[i] = 0ull;

    auto compute = [&](int bf) {
        int kbase = half * 16;
#pragma unroll
        for (int k2 = 0; k2 < 16; k2++) {
            int kk = kbase + k2;
            float a0 = sA[bf][kk][r];
            float a1 = sA[bf][kk][r + 16];
            float4 w0 = *(const float4*)&sW[bf][kk][col];
            float4 w1 = *(const float4*)&sW[bf][kk][col + 4];
            const ull* wp0 = (const ull*)&w0;
            const ull* wp1 = (const ull*)&w1;
            ull ad0 = f32x2_pack(a0, a0);
            ull ad1 = f32x2_pack(a1, a1);
            f32x2_fma(acc[0], ad0, wp0[0]);
            f32x2_fma(acc[1], ad0, wp0[1]);
            f32x2_fma(acc[2], ad0, wp1[0]);
            f32x2_fma(acc[3], ad0, wp1[1]);
            f32x2_fma(acc[4], ad1, wp0[0]);
            f32x2_fma(acc[5], ad1, wp0[1]);
            f32x2_fma(acc[6], ad1, wp1[0]);
            f32x2_fma(acc[7], ad1, wp1[1]);
        }
    };

    // prologue: chunk0 -> regsA -> buf0; chunk1 -> regsB
    ldg(0, raA, rw0A, rw1A);
    sts(0, raA, rw0A, rw1A);
    ldg(1, raB, rw0B, rw1B);
    __syncthreads();

    const int NCH = DD / KC;   // 24
    for (int c = 0; c < NCH; c += 2) {
        // compute chunk c from buf0; stage chunk c+1 into buf1; fetch c+2 -> regsA
        if (c + 1 < NCH) sts(1, raB, rw0B, rw1B);
        if (c + 2 < NCH) ldg(c + 2, raA, rw0A, rw1A);
        compute(0);
        __syncthreads();

        if (c + 1 < NCH) {
            // compute chunk c+1 from buf1; stage c+2 into buf0; fetch c+3 -> regsB
            if (c + 2 < NCH) sts(0, raA, rw0A, rw1A);
            if (c + 3 < NCH) ldg(c + 3, raB, rw0B, rw1B);
            compute(1);
            __syncthreads();
        }
    }

    if (half == 1) {
        float* dst = &sC[tid - 224][0];
#pragma unroll
        for (int i = 0; i < 8; i++) {
            float2 p = f32x2_unpack(acc[i]);
            dst[i * 2] = p.x; dst[i * 2 + 1] = p.y;
        }
    }
    __syncthreads();

    if (half == 0) {
        const float* src = &sC[tid][0];
        float v[16];
#pragma unroll
        for (int i = 0; i < 8; i++) {
            float2 p = f32x2_unpack(acc[i]);
            v[i * 2] = p.x; v[i * 2 + 1] = p.y;
        }
#pragma unroll
        for (int rr = 0; rr < 2; rr++) {
            size_t row = (size_t)(m0 + r + rr * 16);
            if (col < HH) {
                float4 o;
                o.x = tanhf(v[rr*8+0] + src[rr*8+0] + sB[col+0]);
                o.y = tanhf(v[rr*8+1] + src[rr*8+1] + sB[col+1]);
                o.z = tanhf(v[rr*8+2] + src[rr*8+2] + sB[col+2]);
                o.w = tanhf(v[rr*8+3] + src[rr*8+3] + sB[col+3]);
                *(float4*)&out[row * HH + col] = o;
            }
            if (col + 4 < HH) {
                float4 o;
                o.x = tanhf(v[rr*8+4] + src[rr*8+4] + sB[col+4]);
                o.y = tanhf(v[rr*8+5] + src[rr*8+5] + sB[col+5]);
                o.z = tanhf(v[rr*8+6] + src[rr*8+6] + sB[col+6]);
                o.w = tanhf(v[rr*8+7] + src[rr*8+7] + sB[col+7]);
                *(float4*)&out[row * HH + col + 4] = o;
            }
        }
    }
}

extern "C" void kernel_launch(void* const* d_in, const int* in_sizes, int n_in,
                              void* d_out, int out_size) {
    const float* seq   = (const float*)d_in[0];
    const int*   spans = (const int*)d_in[1];
    const int*   mask  = (const int*)d_in[2];
    const float* att_w = (const float*)d_in[3];
    const float* att_b = (const float*)d_in[4];
    const float* ffn_w = (const float*)d_in[5];
    const float* ffn_b = (const float*)d_in[6];
    float*       out   = (float*)d_out;

    k_logits<<<512, 256>>>(seq, att_w, att_b);
    k_span<<<M_TOTAL, 192>>>(seq, spans, mask);
    k_gemm<<<128, 448>>>(ffn_w, ffn_b, out);
}

// round 13
// speedup vs baseline: 1.5324x; 1.2955x over previous
#include <cuda_runtime.h>
#include <cuda_pipeline.h>
#include <cuda_bf16.h>
#include <cstdint>

#define BB 8
#define SS 2048
#define DD 768
#define NSP 512
#define MAXW 30
#define HH 100
#define M_TOTAL (BB*NSP)   /* 4096 */
#define NPAD 112

__device__ float g_logits[BB*SS];
__device__ __nv_bfloat16 g_att_hi[(size_t)M_TOTAL*DD];
__device__ __nv_bfloat16 g_att_lo[(size_t)M_TOTAL*DD];
__device__ __nv_bfloat16 g_wt_hi[(size_t)NPAD*DD];
__device__ __nv_bfloat16 g_wt_lo[(size_t)NPAD*DD];

typedef unsigned long long ull;

__device__ __forceinline__ void f32x2_fma(ull& acc, ull a, ull b) {
    asm("fma.rn.f32x2 %0, %1, %2, %0;" : "+l"(acc) : "l"(a), "l"(b));
}
__device__ __forceinline__ float2 f32x2_unpack(ull v) {
    unsigned int lo, hi;
    asm("mov.b64 {%0, %1}, %2;" : "=r"(lo), "=r"(hi) : "l"(v));
    return make_float2(__uint_as_float(lo), __uint_as_float(hi));
}
__device__ __forceinline__ uint32_t smem_to_u32(const void* p) {
    uint32_t a;
    asm("{ .reg .u64 t; cvta.to.shared.u64 t, %1; cvt.u32.u64 %0, t; }" : "=r"(a) : "l"(p));
    return a;
}
__device__ __forceinline__ void ldmx4(uint32_t* r, uint32_t addr) {
    asm volatile("ldmatrix.sync.aligned.m8n8.x4.shared.b16 {%0,%1,%2,%3}, [%4];"
        : "=r"(r[0]), "=r"(r[1]), "=r"(r[2]), "=r"(r[3]) : "r"(addr));
}
__device__ __forceinline__ void ldmx2(uint32_t* r, uint32_t addr) {
    asm volatile("ldmatrix.sync.aligned.m8n8.x2.shared.b16 {%0,%1}, [%2];"
        : "=r"(r[0]), "=r"(r[1]) : "r"(addr));
}
__device__ __forceinline__ void mma_bf16(float* c, const uint32_t* a, const uint32_t* b) {
    asm volatile("mma.sync.aligned.m16n8k16.row.col.f32.bf16.bf16.f32 "
        "{%0,%1,%2,%3}, {%4,%5,%6,%7}, {%8,%9}, {%0,%1,%2,%3};"
        : "+f"(c[0]), "+f"(c[1]), "+f"(c[2]), "+f"(c[3])
        : "r"(a[0]), "r"(a[1]), "r"(a[2]), "r"(a[3]), "r"(b[0]), "r"(b[1]));
}

// -------- Kernel 0: transpose + bf16-split W into [112 x 768] K-major ----------
__global__ void __launch_bounds__(192) k_wprep(const float* __restrict__ W) {
    int n = blockIdx.x;                 // 0..111
    for (int k = threadIdx.x; k < DD; k += 192) {
        float w = (n < HH) ? W[(size_t)k * HH + n] : 0.f;
        __nv_bfloat16 hi = __float2bfloat16(w);
        float lo = w - __bfloat162float(hi);
        g_wt_hi[(size_t)n * DD + k] = hi;
        g_wt_lo[(size_t)n * DD + k] = __float2bfloat16(lo);
    }
}

// -------- Kernel 1: logits via cp.async double-buffered streaming (R9) ---------
__global__ void __launch_bounds__(256) k_logits(const float* __restrict__ seq,
                                                const float* __restrict__ att_w,
                                                const float* __restrict__ att_b) {
    __shared__ float4 sbuf[2][8 * (DD / 4)];

    int tid = threadIdx.x, warp = tid >> 5, lane = tid & 31;
    size_t base = (size_t)blockIdx.x * 32;
    const float4* src = (const float4*)seq + base * (DD / 4);

#pragma unroll
    for (int k = 0; k < 6; k++) {
        int idx = tid + k * 256;
        __pipeline_memcpy_async(&sbuf[0][idx], &src[idx], 16);
    }
    __pipeline_commit();
#pragma unroll
    for (int k = 0; k < 6; k++) {
        int idx = tid + k * 256;
        __pipeline_memcpy_async(&sbuf[1][idx], &src[1536 + idx], 16);
    }
    __pipeline_commit();

    float4 wreg[6];
    const float4* w4 = (const float4*)att_w;
#pragma unroll
    for (int j = 0; j < 6; j++) wreg[j] = __ldg(&w4[lane + 32 * j]);
    float bconst = __ldg(att_b);

    for (int s = 0; s < 4; s++) {
        if (s < 3) __pipeline_wait_prior(1);
        else       __pipeline_wait_prior(0);
        __syncthreads();

        const float4* row = &sbuf[s & 1][warp * (DD / 4)];
        float4 x[6];
#pragma unroll
        for (int j = 0; j < 6; j++) x[j] = row[lane + 32 * j];
        ull acc = 0ull;
#pragma unroll
        for (int j = 0; j < 6; j++) {
            const ull* xp = (const ull*)&x[j];
            const ull* wp = (const ull*)&wreg[j];
            f32x2_fma(acc, xp[0], wp[0]);
            f32x2_fma(acc, xp[1], wp[1]);
        }
        float2 p = f32x2_unpack(acc);
        float sum = p.x + p.y;
#pragma unroll
        for (int o = 16; o > 0; o >>= 1) sum += __shfl_xor_sync(0xffffffffu, sum, o);
        if (lane == 0) g_logits[base + s * 8 + warp] = sum + bconst;
        __syncthreads();

        if (s + 2 < 4) {
            const float4* g = src + (size_t)(s + 2) * 1536;
#pragma unroll
            for (int k = 0; k < 6; k++) {
                int idx = tid + k * 256;
                __pipeline_memcpy_async(&sbuf[s & 1][idx], &g[idx], 16);
            }
            __pipeline_commit();
        }
    }
}

// -------- Kernel 2: span softmax + weighted sum -> bf16 hi/lo -------------------
__global__ void __launch_bounds__(192) k_span(const float* __restrict__ seq,
                                              const int* __restrict__ spans,
                                              const int* __restrict__ mask) {
    __shared__ float s_attn[MAXW];
    __shared__ int   s_start, s_cnt;
    int sp  = blockIdx.x;
    int b   = sp >> 9;
    int tid = threadIdx.x;

    if (tid < 32) {
        int start = spans[sp * 2];
        int cnt   = spans[sp * 2 + 1] - start;
        float lg = (tid < cnt) ? g_logits[b * SS + start + tid] : -1e30f;
        float mx = lg;
#pragma unroll
        for (int o = 16; o > 0; o >>= 1) mx = fmaxf(mx, __shfl_xor_sync(0xffffffffu, mx, o));
        float ex = (tid < cnt) ? expf(lg - mx) : 0.f;
        float sm = ex;
#pragma unroll
        for (int o = 16; o > 0; o >>= 1) sm += __shfl_xor_sync(0xffffffffu, sm, o);
        float mk = (float)mask[sp];
        if (tid < MAXW) s_attn[tid] = ex / sm * mk;
        if (tid == 0) { s_start = start; s_cnt = cnt; }
    }
    __syncthreads();

    int start = s_start, cnt = s_cnt;
    const float4* base = (const float4*)seq + (size_t)(b * SS + start) * (DD / 4) + tid;
    float4 acc = make_float4(0.f, 0.f, 0.f, 0.f);
#pragma unroll 4
    for (int w = 0; w < cnt; w++) {
        float a  = s_attn[w];
        float4 v = base[(size_t)w * (DD / 4)];
        acc.x += a * v.x; acc.y += a * v.y; acc.z += a * v.z; acc.w += a * v.w;
    }

    size_t idx = (size_t)sp * DD + tid * 4;
    __nv_bfloat16 h0 = __float2bfloat16(acc.x);
    __nv_bfloat16 h1 = __float2bfloat16(acc.y);
    __nv_bfloat16 h2 = __float2bfloat16(acc.z);
    __nv_bfloat16 h3 = __float2bfloat16(acc.w);
    *(__nv_bfloat162*)&g_att_hi[idx]     = __halves2bfloat162(h0, h1);
    *(__nv_bfloat162*)&g_att_hi[idx + 2] = __halves2bfloat162(h2, h3);
    __nv_bfloat16 l0 = __float2bfloat16(acc.x - __bfloat162float(h0));
    __nv_bfloat16 l1 = __float2bfloat16(acc.y - __bfloat162float(h1));
    __nv_bfloat16 l2 = __float2bfloat16(acc.z - __bfloat162float(h2));
    __nv_bfloat16 l3 = __float2bfloat16(acc.w - __bfloat162float(h3));
    *(__nv_bfloat162*)&g_att_lo[idx]     = __halves2bfloat162(l0, l1);
    *(__nv_bfloat162*)&g_att_lo[idx + 2] = __halves2bfloat162(l2, l3);
}

// -------- Kernel 3: mma.sync bf16 3-pass GEMM + bias + tanh ---------------------
// grid = 128 (M-tile 32), block 256 = 8 warps = (ms x nh x kh).
// smem rows padded to 144B -> conflict-free ldmatrix. cp.async double buffer.
#define SM_A_HI 0                 /* 2 bufs x 4608  (32 x 144) */
#define SM_A_LO 9216
#define SM_W_HI 18432             /* 2 bufs x 16128 (112 x 144) */
#define SM_W_LO 50688
#define SM_GEMM_TOTAL 82944

__global__ void __launch_bounds__(256) k_gemm(const float* __restrict__ bias,
                                              float* __restrict__ out) {
    extern __shared__ __align__(16) char smem[];
    uint32_t sb = smem_to_u32(smem);
    int tid = threadIdx.x, warp = tid >> 5, lane = tid & 31;
    int ms = warp & 1, nh = (warp >> 1) & 1, kh = warp >> 2;
    int m0 = blockIdx.x * 32;
    int g = lane >> 2, tk = lane & 3;

    float acc[7][4];
#pragma unroll
    for (int t = 0; t < 7; t++)
#pragma unroll
        for (int q = 0; q < 4; q++) acc[t][q] = 0.f;

    const char* Ahi = (const char*)g_att_hi + (size_t)m0 * DD * 2;
    const char* Alo = (const char*)g_att_lo + (size_t)m0 * DD * 2;
    const char* Whi = (const char*)g_wt_hi;
    const char* Wlo = (const char*)g_wt_lo;

    auto load_chunk = [&](int c, int buf) {
        int koff = c * 64;                       // bf16 index along K
        {   // A: 32 rows x 8 x 16B pieces, 256 threads -> 1 piece each (hi+lo)
            int row = tid >> 3, j = tid & 7;
            size_t so = ((size_t)row * DD + koff + j * 8) * 2;
            uint32_t d = (uint32_t)(buf * 4608 + row * 144 + j * 16);
            __pipeline_memcpy_async(smem + SM_A_HI + d, Ahi + so, 16);
            __pipeline_memcpy_async(smem + SM_A_LO + d, Alo + so, 16);
        }
        for (int p = tid; p < 896; p += 256) {   // W: 112 rows x 8 pieces
            int row = p >> 3, j = p & 7;
            size_t so = ((size_t)row * DD + koff + j * 8) * 2;
            uint32_t d = (uint32_t)(buf * 16128 + row * 144 + j * 16);
            __pipeline_memcpy_async(smem + SM_W_HI + d, Whi + so, 16);
            __pipeline_memcpy_async(smem + SM_W_LO + d, Wlo + so, 16);
        }
    };

    int row_in = lane & 15, khf = lane >> 4;     // A ldmatrix lane mapping
    int brow = lane & 7, bko = (lane & 8) ? 8 : 0;  // B ldmatrix lane mapping

    auto compute = [&](int buf) {
#pragma unroll
        for (int s = 0; s < 2; s++) {
            int k0 = (kh * 2 + s) * 16;          // bf16 index within chunk
            uint32_t addrA = sb + SM_A_HI + buf * 4608
                           + (ms * 16 + row_in) * 144 + (k0 + khf * 8) * 2;
            uint32_t ahi[4], alo[4];
            ldmx4(ahi, addrA);
            ldmx4(alo, addrA + (SM_A_LO - SM_A_HI));
#pragma unroll
            for (int t = 0; t < 7; t++) {
                int n0 = (nh * 7 + t) * 8;
                uint32_t addrB = sb + SM_W_HI + buf * 16128
                               + (n0 + brow) * 144 + (k0 + bko) * 2;
                uint32_t bhi[2], blo[2];
                ldmx2(bhi, addrB);
                ldmx2(blo, addrB + (SM_W_LO - SM_W_HI));
                mma_bf16(acc[t], ahi, bhi);
                mma_bf16(acc[t], ahi, blo);
                mma_bf16(acc[t], alo, bhi);
            }
        }
    };

    load_chunk(0, 0);
    __pipeline_commit();

    for (int c = 0; c < 12; c++) {
        if (c + 1 < 12) { load_chunk(c + 1, (c + 1) & 1); __pipeline_commit(); }
        if (c + 1 < 12) __pipeline_wait_prior(1);
        else            __pipeline_wait_prior(0);
        __syncthreads();
        compute(c & 1);
        __syncthreads();
    }

    // combine k-halves through smem (reuse A region: 14336B <= 18432B)
    float* sc = (float*)smem;
    if (kh == 1) {
#pragma unroll
        for (int t = 0; t < 7; t++) {
            int idx = (((ms * 2 + nh) * 7 + t) * 32 + lane) * 4;
            sc[idx + 0] = acc[t][0]; sc[idx + 1] = acc[t][1];
            sc[idx + 2] = acc[t][2]; sc[idx + 3] = acc[t][3];
        }
    }
    __syncthreads();

    if (kh == 0) {
        int row0 = m0 + ms * 16 + g;
#pragma unroll
        for (int t = 0; t < 7; t++) {
            int n0 = (nh * 7 + t) * 8;
            int col = n0 + tk * 2;
            if (col < HH) {
                int idx = (((ms * 2 + nh) * 7 + t) * 32 + lane) * 4;
                float b0 = __ldg(&bias[col]), b1 = __ldg(&bias[col + 1]);
                float2 v0, v1;
                v0.x = tanhf(acc[t][0] + sc[idx + 0] + b0);
                v0.y = tanhf(acc[t][1] + sc[idx + 1] + b1);
                v1.x = tanhf(acc[t][2] + sc[idx + 2] + b0);
                v1.y = tanhf(acc[t][3] + sc[idx + 3] + b1);
                *(float2*)&out[(size_t)row0 * HH + col]       = v0;
                *(float2*)&out[(size_t)(row0 + 8) * HH + col] = v1;
            }
        }
    }
}

extern "C" void kernel_launch(void* const* d_in, const int* in_sizes, int n_in,
                              void* d_out, int out_size) {
    const float* seq   = (const float*)d_in[0];
    const int*   spans = (const int*)d_in[1];
    const int*   mask  = (const int*)d_in[2];
    const float* att_w = (const float*)d_in[3];
    const float* att_b = (const float*)d_in[4];
    const float* ffn_w = (const float*)d_in[5];
    const float* ffn_b = (const float*)d_in[6];
    float*       out   = (float*)d_out;

    cudaFuncSetAttribute(k_gemm, cudaFuncAttributeMaxDynamicSharedMemorySize, SM_GEMM_TOTAL);

    k_wprep<<<NPAD, 192>>>(ffn_w);
    k_logits<<<512, 256>>>(seq, att_w, att_b);
    k_span<<<M_TOTAL, 192>>>(seq, spans, mask);
    k_gemm<<<128, 256, SM_GEMM_TOTAL>>>(ffn_b, out);
}

// round 14
// speedup vs baseline: 1.5336x; 1.0008x over previous
#include <cuda_runtime.h>
#include <cuda_pipeline.h>
#include <cuda_bf16.h>
#include <cstdint>

#define BB 8
#define SS 2048
#define DD 768
#define NSP 512
#define MAXW 30
#define HH 100
#define M_TOTAL (BB*NSP)   /* 4096 */
#define NPAD 112

__device__ float g_logits[BB*SS];
__device__ __nv_bfloat16 g_att_hi[(size_t)M_TOTAL*DD];
__device__ __nv_bfloat16 g_att_lo[(size_t)M_TOTAL*DD];
__device__ __nv_bfloat16 g_wt_hi[(size_t)NPAD*DD];
__device__ __nv_bfloat16 g_wt_lo[(size_t)NPAD*DD];

typedef unsigned long long ull;

__device__ __forceinline__ void f32x2_fma(ull& acc, ull a, ull b) {
    asm("fma.rn.f32x2 %0, %1, %2, %0;" : "+l"(acc) : "l"(a), "l"(b));
}
__device__ __forceinline__ float2 f32x2_unpack(ull v) {
    unsigned int lo, hi;
    asm("mov.b64 {%0, %1}, %2;" : "=r"(lo), "=r"(hi) : "l"(v));
    return make_float2(__uint_as_float(lo), __uint_as_float(hi));
}
__device__ __forceinline__ uint32_t smem_to_u32(const void* p) {
    uint32_t a;
    asm("{ .reg .u64 t; cvta.to.shared.u64 t, %1; cvt.u32.u64 %0, t; }" : "=r"(a) : "l"(p));
    return a;
}
__device__ __forceinline__ void ldmx4(uint32_t* r, uint32_t addr) {
    asm volatile("ldmatrix.sync.aligned.m8n8.x4.shared.b16 {%0,%1,%2,%3}, [%4];"
        : "=r"(r[0]), "=r"(r[1]), "=r"(r[2]), "=r"(r[3]) : "r"(addr));
}
__device__ __forceinline__ void ldmx2(uint32_t* r, uint32_t addr) {
    asm volatile("ldmatrix.sync.aligned.m8n8.x2.shared.b16 {%0,%1}, [%2];"
        : "=r"(r[0]), "=r"(r[1]) : "r"(addr));
}
__device__ __forceinline__ void mma_bf16(float* c, const uint32_t* a, const uint32_t* b) {
    asm volatile("mma.sync.aligned.m16n8k16.row.col.f32.bf16.bf16.f32 "
        "{%0,%1,%2,%3}, {%4,%5,%6,%7}, {%8,%9}, {%0,%1,%2,%3};"
        : "+f"(c[0]), "+f"(c[1]), "+f"(c[2]), "+f"(c[3])
        : "r"(a[0]), "r"(a[1]), "r"(a[2]), "r"(a[3]), "r"(b[0]), "r"(b[1]));
}

// -------- Kernel 0: transpose + bf16-split W into [112 x 768] K-major ----------
__global__ void __launch_bounds__(192) k_wprep(const float* __restrict__ W) {
    int n = blockIdx.x;
    for (int k = threadIdx.x; k < DD; k += 192) {
        float w = (n < HH) ? W[(size_t)k * HH + n] : 0.f;
        __nv_bfloat16 hi = __float2bfloat16(w);
        float lo = w - __bfloat162float(hi);
        g_wt_hi[(size_t)n * DD + k] = hi;
        g_wt_lo[(size_t)n * DD + k] = __float2bfloat16(lo);
    }
}

// -------- Kernel 1: logits via cp.async double-buffered streaming (R9) ---------
__global__ void __launch_bounds__(256) k_logits(const float* __restrict__ seq,
                                                const float* __restrict__ att_w,
                                                const float* __restrict__ att_b) {
    __shared__ float4 sbuf[2][8 * (DD / 4)];

    int tid = threadIdx.x, warp = tid >> 5, lane = tid & 31;
    size_t base = (size_t)blockIdx.x * 32;
    const float4* src = (const float4*)seq + base * (DD / 4);

#pragma unroll
    for (int k = 0; k < 6; k++) {
        int idx = tid + k * 256;
        __pipeline_memcpy_async(&sbuf[0][idx], &src[idx], 16);
    }
    __pipeline_commit();
#pragma unroll
    for (int k = 0; k < 6; k++) {
        int idx = tid + k * 256;
        __pipeline_memcpy_async(&sbuf[1][idx], &src[1536 + idx], 16);
    }
    __pipeline_commit();

    float4 wreg[6];
    const float4* w4 = (const float4*)att_w;
#pragma unroll
    for (int j = 0; j < 6; j++) wreg[j] = __ldg(&w4[lane + 32 * j]);
    float bconst = __ldg(att_b);

    for (int s = 0; s < 4; s++) {
        if (s < 3) __pipeline_wait_prior(1);
        else       __pipeline_wait_prior(0);
        __syncthreads();

        const float4* row = &sbuf[s & 1][warp * (DD / 4)];
        float4 x[6];
#pragma unroll
        for (int j = 0; j < 6; j++) x[j] = row[lane + 32 * j];
        ull acc = 0ull;
#pragma unroll
        for (int j = 0; j < 6; j++) {
            const ull* xp = (const ull*)&x[j];
            const ull* wp = (const ull*)&wreg[j];
            f32x2_fma(acc, xp[0], wp[0]);
            f32x2_fma(acc, xp[1], wp[1]);
        }
        float2 p = f32x2_unpack(acc);
        float sum = p.x + p.y;
#pragma unroll
        for (int o = 16; o > 0; o >>= 1) sum += __shfl_xor_sync(0xffffffffu, sum, o);
        if (lane == 0) g_logits[base + s * 8 + warp] = sum + bconst;
        __syncthreads();

        if (s + 2 < 4) {
            const float4* g = src + (size_t)(s + 2) * 1536;
#pragma unroll
            for (int k = 0; k < 6; k++) {
                int idx = tid + k * 256;
                __pipeline_memcpy_async(&sbuf[s & 1][idx], &g[idx], 16);
            }
            __pipeline_commit();
        }
    }
}

// -------- Kernel 2: span softmax + weighted sum -> bf16 hi/lo -------------------
__global__ void __launch_bounds__(192) k_span(const float* __restrict__ seq,
                                              const int* __restrict__ spans,
                                              const int* __restrict__ mask) {
    __shared__ float s_attn[MAXW];
    __shared__ int   s_start, s_cnt;
    int sp  = blockIdx.x;
    int b   = sp >> 9;
    int tid = threadIdx.x;

    if (tid < 32) {
        int start = spans[sp * 2];
        int cnt   = spans[sp * 2 + 1] - start;
        float lg = (tid < cnt) ? g_logits[b * SS + start + tid] : -1e30f;
        float mx = lg;
#pragma unroll
        for (int o = 16; o > 0; o >>= 1) mx = fmaxf(mx, __shfl_xor_sync(0xffffffffu, mx, o));
        float ex = (tid < cnt) ? expf(lg - mx) : 0.f;
        float sm = ex;
#pragma unroll
        for (int o = 16; o > 0; o >>= 1) sm += __shfl_xor_sync(0xffffffffu, sm, o);
        float mk = (float)mask[sp];
        if (tid < MAXW) s_attn[tid] = ex / sm * mk;
        if (tid == 0) { s_start = start; s_cnt = cnt; }
    }
    __syncthreads();

    int start = s_start, cnt = s_cnt;
    const float4* base = (const float4*)seq + (size_t)(b * SS + start) * (DD / 4) + tid;
    float4 acc = make_float4(0.f, 0.f, 0.f, 0.f);
#pragma unroll 4
    for (int w = 0; w < cnt; w++) {
        float a  = s_attn[w];
        float4 v = base[(size_t)w * (DD / 4)];
        acc.x += a * v.x; acc.y += a * v.y; acc.z += a * v.z; acc.w += a * v.w;
    }

    size_t idx = (size_t)sp * DD + tid * 4;
    __nv_bfloat16 h0 = __float2bfloat16(acc.x);
    __nv_bfloat16 h1 = __float2bfloat16(acc.y);
    __nv_bfloat16 h2 = __float2bfloat16(acc.z);
    __nv_bfloat16 h3 = __float2bfloat16(acc.w);
    *(__nv_bfloat162*)&g_att_hi[idx]     = __halves2bfloat162(h0, h1);
    *(__nv_bfloat162*)&g_att_hi[idx + 2] = __halves2bfloat162(h2, h3);
    __nv_bfloat16 l0 = __float2bfloat16(acc.x - __bfloat162float(h0));
    __nv_bfloat16 l1 = __float2bfloat16(acc.y - __bfloat162float(h1));
    __nv_bfloat16 l2 = __float2bfloat16(acc.z - __bfloat162float(h2));
    __nv_bfloat16 l3 = __float2bfloat16(acc.w - __bfloat162float(h3));
    *(__nv_bfloat162*)&g_att_lo[idx]     = __halves2bfloat162(l0, l1);
    *(__nv_bfloat162*)&g_att_lo[idx + 2] = __halves2bfloat162(l2, l3);
}

// -------- Kernel 3: mma.sync bf16 3-pass GEMM + bias + tanh ---------------------
// grid = 128 (M-tile 32), block 512 = 16 warps = (ms x nh x kh[0..3]).
// Each warp does ONE 16-wide kstep per chunk -> 252 HMMA/warp, 4 warps/SMSP.
#define SM_A_HI 0                 /* 2 bufs x 4608  (32 x 144) */
#define SM_A_LO 9216
#define SM_W_HI 18432             /* 2 bufs x 16128 (112 x 144) */
#define SM_W_LO 50688
#define SM_GEMM_TOTAL 82944

__global__ void __launch_bounds__(512) k_gemm(const float* __restrict__ bias,
                                              float* __restrict__ out) {
    extern __shared__ __align__(16) char smem[];
    uint32_t sb = smem_to_u32(smem);
    int tid = threadIdx.x, warp = tid >> 5, lane = tid & 31;
    int ms = warp & 1, nh = (warp >> 1) & 1, kh = warp >> 2;   // kh 0..3
    int m0 = blockIdx.x * 32;
    int g = lane >> 2, tk = lane & 3;

    float acc[7][4];
#pragma unroll
    for (int t = 0; t < 7; t++)
#pragma unroll
        for (int q = 0; q < 4; q++) acc[t][q] = 0.f;

    const char* Ahi = (const char*)g_att_hi + (size_t)m0 * DD * 2;
    const char* Alo = (const char*)g_att_lo + (size_t)m0 * DD * 2;
    const char* Whi = (const char*)g_wt_hi;
    const char* Wlo = (const char*)g_wt_lo;

    auto load_chunk = [&](int c, int buf) {
        int koff = c * 64;
        if (tid < 256) {    // A: 32 rows x 8 pieces (hi+lo)
            int row = tid >> 3, j = tid & 7;
            size_t so = ((size_t)row * DD + koff + j * 8) * 2;
            uint32_t d = (uint32_t)(buf * 4608 + row * 144 + j * 16);
            __pipeline_memcpy_async(smem + SM_A_HI + d, Ahi + so, 16);
            __pipeline_memcpy_async(smem + SM_A_LO + d, Alo + so, 16);
        }
        for (int p = tid; p < 896; p += 512) {   // W: 112 rows x 8 pieces
            int row = p >> 3, j = p & 7;
            size_t so = ((size_t)row * DD + koff + j * 8) * 2;
            uint32_t d = (uint32_t)(buf * 16128 + row * 144 + j * 16);
            __pipeline_memcpy_async(smem + SM_W_HI + d, Whi + so, 16);
            __pipeline_memcpy_async(smem + SM_W_LO + d, Wlo + so, 16);
        }
    };

    int row_in = lane & 15, khf = lane >> 4;
    int brow = lane & 7, bko = (lane & 8) ? 8 : 0;

    auto compute = [&](int buf) {
        int k0 = kh * 16;                        // this warp's single kstep
        uint32_t addrA = sb + SM_A_HI + buf * 4608
                       + (ms * 16 + row_in) * 144 + (k0 + khf * 8) * 2;
        uint32_t ahi[4], alo[4];
        ldmx4(ahi, addrA);
        ldmx4(alo, addrA + (SM_A_LO - SM_A_HI));
#pragma unroll
        for (int t = 0; t < 7; t++) {
            int n0 = (nh * 7 + t) * 8;
            uint32_t addrB = sb + SM_W_HI + buf * 16128
                           + (n0 + brow) * 144 + (k0 + bko) * 2;
            uint32_t bhi[2], blo[2];
            ldmx2(bhi, addrB);
            ldmx2(blo, addrB + (SM_W_LO - SM_W_HI));
            mma_bf16(acc[t], ahi, bhi);
            mma_bf16(acc[t], ahi, blo);
            mma_bf16(acc[t], alo, bhi);
        }
    };

    load_chunk(0, 0);
    __pipeline_commit();

    for (int c = 0; c < 12; c++) {
        if (c + 1 < 12) { load_chunk(c + 1, (c + 1) & 1); __pipeline_commit(); }
        if (c + 1 < 12) __pipeline_wait_prior(1);
        else            __pipeline_wait_prior(0);
        __syncthreads();
        compute(c & 1);
        __syncthreads();
    }

    // combine 4 k-partials through smem (3 x 14336B overlays A/W buffers)
    float* sc = (float*)smem;
    if (kh > 0) {
        float* dst = sc + (size_t)(kh - 1) * 3584;     // 3584 floats per group
#pragma unroll
        for (int t = 0; t < 7; t++) {
            int idx = (((ms * 2 + nh) * 7 + t) * 32 + lane) * 4;
            dst[idx + 0] = acc[t][0]; dst[idx + 1] = acc[t][1];
            dst[idx + 2] = acc[t][2]; dst[idx + 3] = acc[t][3];
        }
    }
    __syncthreads();

    if (kh == 0) {
        int row0 = m0 + ms * 16 + g;
#pragma unroll
        for (int t = 0; t < 7; t++) {
            int n0 = (nh * 7 + t) * 8;
            int col = n0 + tk * 2;
            if (col < HH) {
                int idx = (((ms * 2 + nh) * 7 + t) * 32 + lane) * 4;
                float p0 = sc[idx + 0] + sc[3584 + idx + 0] + sc[7168 + idx + 0];
                float p1 = sc[idx + 1] + sc[3584 + idx + 1] + sc[7168 + idx + 1];
                float p2 = sc[idx + 2] + sc[3584 + idx + 2] + sc[7168 + idx + 2];
                float p3 = sc[idx + 3] + sc[3584 + idx + 3] + sc[7168 + idx + 3];
                float b0 = __ldg(&bias[col]), b1 = __ldg(&bias[col + 1]);
                float2 v0, v1;
                v0.x = tanhf(acc[t][0] + p0 + b0);
                v0.y = tanhf(acc[t][1] + p1 + b1);
                v1.x = tanhf(acc[t][2] + p2 + b0);
                v1.y = tanhf(acc[t][3] + p3 + b1);
                *(float2*)&out[(size_t)row0 * HH + col]       = v0;
                *(float2*)&out[(size_t)(row0 + 8) * HH + col] = v1;
            }
        }
    }
}

extern "C" void kernel_launch(void* const* d_in, const int* in_sizes, int n_in,
                              void* d_out, int out_size) {
    const float* seq   = (const float*)d_in[0];
    const int*   spans = (const int*)d_in[1];
    const int*   mask  = (const int*)d_in[2];
    const float* att_w = (const float*)d_in[3];
    const float* att_b = (const float*)d_in[4];
    const float* ffn_w = (const float*)d_in[5];
    const float* ffn_b = (const float*)d_in[6];
    float*       out   = (float*)d_out;

    cudaFuncSetAttribute(k_gemm, cudaFuncAttributeMaxDynamicSharedMemorySize, SM_GEMM_TOTAL);

    k_wprep<<<NPAD, 192>>>(ffn_w);
    k_logits<<<512, 256>>>(seq, att_w, att_b);
    k_span<<<M_TOTAL, 192>>>(seq, spans, mask);
    k_gemm<<<128, 512, SM_GEMM_TOTAL>>>(ffn_b, out);
}